// round 11
// baseline (speedup 1.0000x reference)
#include <cuda_runtime.h>

#define B_  16
#define T_  1024
#define D_  1024
#define HS_ 64
#define H_  16
#define M_  (B_*T_)   // 16384

typedef unsigned long long u64_t;

// ---- packed f32x2 helpers (syntax per ptx_helpers.cuh PACK/UNPACK_F32X2) ----
__device__ __forceinline__ u64_t pack_dup(float v) {
    u64_t r; unsigned u = __float_as_uint(v);
    asm("mov.b64 %0, {%1, %1};" : "=l"(r) : "r"(u));
    return r;
}
__device__ __forceinline__ void fma2(u64_t &d, u64_t a, u64_t b) {
    asm("fma.rn.f32x2 %0, %1, %2, %0;" : "+l"(d) : "l"(a), "l"(b));
}
__device__ __forceinline__ void unpack2(u64_t v, float &lo, float &hi) {
    unsigned a, b;
    asm("mov.b64 {%0, %1}, %2;" : "=r"(a), "=r"(b) : "l"(v));
    lo = __uint_as_float(a); hi = __uint_as_float(b);
}

// Scratch (device globals — no allocation allowed)
__device__ float g_q [M_*HS_];
__device__ float g_k [M_*HS_];
__device__ float g_v [M_*HS_];
__device__ float g_ho[M_*HS_];
__device__ float g_wp[HS_*D_];

// ---------------------------------------------------------------------------
// Fold Wp: Wp_eff[j][e] = sum_h Wp[h*HS+j][e]   (tile() collapse)
// ---------------------------------------------------------------------------
__global__ void fold_wp_kernel(const float* __restrict__ Wp) {
    int idx = blockIdx.x * blockDim.x + threadIdx.x;   // 0..65535
    int j = idx >> 10;          // /1024
    int e = idx & 1023;
    float s = 0.f;
    #pragma unroll
    for (int h = 0; h < H_; ++h) s += Wp[(h*HS_ + j)*D_ + e];
    g_wp[idx] = s;
    (void)e; (void)j;
}

// ---------------------------------------------------------------------------
// Fused QKV projection: {q,k,v}[M,64] = x[M,1024] @ {Wq,Wk,Wv}[1024,64]
// One As tile load feeds all three accumulator sets (3x less x traffic).
// Software-pipelined + packed f32x2 FMA (FFMA2): column-paired accumulators,
// bit-identical fp32 math, half the fma-pipe issues.
// Tile: BM=64, BN=64(=HS), BK=32, 256 threads, 4x4 micro-tile x 3 outputs.
// ---------------------------------------------------------------------------
__global__ void __launch_bounds__(256)
qkv_gemm_kernel(const float* __restrict__ x,
                const float* __restrict__ Wq,
                const float* __restrict__ Wk,
                const float* __restrict__ Wv) {
    const int BM = 64, BK = 32;
    __shared__ float As [BM][BK+1];   // [64][33]
    __shared__ float Wqs[BK][HS_];
    __shared__ float Wks[BK][HS_];
    __shared__ float Wvs[BK][HS_];

    int tid = threadIdx.x;            // 256
    int tx  = tid & 15, ty = tid >> 4;
    int row0 = blockIdx.x * BM;

    // Per-thread load coordinates (fixed across tiles)
    const int ar0 = (tid      ) >> 3, ac0 = (tid      ) & 7;  // A elem 0
    const int ar1 = (tid + 256) >> 3, ac1 = (tid + 256) & 7;  // A elem 1
    const int wr0 = (tid      ) >> 4, wc0 = (tid      ) & 15; // W elem 0
    const int wr1 = (tid + 256) >> 4, wc1 = (tid + 256) & 15; // W elem 1

    // Packed accumulators: [i][j2] covers columns (tx*4+2*j2, tx*4+2*j2+1)
    u64_t aq2[4][2] = {}, ak2[4][2] = {}, av2[4][2] = {};

    float4 pa0, pa1, pq0, pq1, pk0, pk1, pv0, pv1;

    // Prefetch tile 0
    {
        const int k0 = 0;
        pa0 = *(const float4*)&x[(size_t)(row0 + ar0)*D_ + k0 + ac0*4];
        pa1 = *(const float4*)&x[(size_t)(row0 + ar1)*D_ + k0 + ac1*4];
        size_t o0 = (size_t)(k0 + wr0)*HS_ + wc0*4;
        size_t o1 = (size_t)(k0 + wr1)*HS_ + wc1*4;
        pq0 = *(const float4*)&Wq[o0]; pq1 = *(const float4*)&Wq[o1];
        pk0 = *(const float4*)&Wk[o0]; pk1 = *(const float4*)&Wk[o1];
        pv0 = *(const float4*)&Wv[o0]; pv1 = *(const float4*)&Wv[o1];
    }

    for (int k0 = 0; k0 < D_; k0 += BK) {
        // Commit prefetched tile to smem
        As[ar0][ac0*4+0] = pa0.x; As[ar0][ac0*4+1] = pa0.y;
        As[ar0][ac0*4+2] = pa0.z; As[ar0][ac0*4+3] = pa0.w;
        As[ar1][ac1*4+0] = pa1.x; As[ar1][ac1*4+1] = pa1.y;
        As[ar1][ac1*4+2] = pa1.z; As[ar1][ac1*4+3] = pa1.w;
        *(float4*)&Wqs[wr0][wc0*4] = pq0; *(float4*)&Wqs[wr1][wc1*4] = pq1;
        *(float4*)&Wks[wr0][wc0*4] = pk0; *(float4*)&Wks[wr1][wc1*4] = pk1;
        *(float4*)&Wvs[wr0][wc0*4] = pv0; *(float4*)&Wvs[wr1][wc1*4] = pv1;
        __syncthreads();

        // Issue next tile's loads (latency hidden behind compute below)
        int kn = k0 + BK;
        if (kn < D_) {
            pa0 = *(const float4*)&x[(size_t)(row0 + ar0)*D_ + kn + ac0*4];
            pa1 = *(const float4*)&x[(size_t)(row0 + ar1)*D_ + kn + ac1*4];
            size_t o0 = (size_t)(kn + wr0)*HS_ + wc0*4;
            size_t o1 = (size_t)(kn + wr1)*HS_ + wc1*4;
            pq0 = *(const float4*)&Wq[o0]; pq1 = *(const float4*)&Wq[o1];
            pk0 = *(const float4*)&Wk[o0]; pk1 = *(const float4*)&Wk[o1];
            pv0 = *(const float4*)&Wv[o0]; pv1 = *(const float4*)&Wv[o1];
        }

        #pragma unroll
        for (int k = 0; k < BK; ++k) {
            u64_t a2[4];
            #pragma unroll
            for (int i = 0; i < 4; ++i) a2[i] = pack_dup(As[ty*4+i][k]);
            u64_t bq2[2], bk2[2], bv2[2];
            #pragma unroll
            for (int j2 = 0; j2 < 2; ++j2) {
                bq2[j2] = *(const u64_t*)&Wqs[k][tx*4 + 2*j2];
                bk2[j2] = *(const u64_t*)&Wks[k][tx*4 + 2*j2];
                bv2[j2] = *(const u64_t*)&Wvs[k][tx*4 + 2*j2];
            }
            #pragma unroll
            for (int i = 0; i < 4; ++i)
                #pragma unroll
                for (int j2 = 0; j2 < 2; ++j2) {
                    fma2(aq2[i][j2], a2[i], bq2[j2]);
                    fma2(ak2[i][j2], a2[i], bk2[j2]);
                    fma2(av2[i][j2], a2[i], bv2[j2]);
                }
        }
        __syncthreads();
    }

    #pragma unroll
    for (int i = 0; i < 4; ++i) {
        size_t r = row0 + ty*4 + i;
        float v0, v1, v2, v3;
        unpack2(aq2[i][0], v0, v1); unpack2(aq2[i][1], v2, v3);
        *(float4*)&g_q[r*HS_ + tx*4] = make_float4(v0, v1, v2, v3);
        unpack2(ak2[i][0], v0, v1); unpack2(ak2[i][1], v2, v3);
        *(float4*)&g_k[r*HS_ + tx*4] = make_float4(v0, v1, v2, v3);
        unpack2(av2[i][0], v0, v1); unpack2(av2[i][1], v2, v3);
        *(float4*)&g_v[r*HS_ + tx*4] = make_float4(v0, v1, v2, v3);
    }
}

// ---------------------------------------------------------------------------
// Causal flash attention, single head HS=64.
// grid (T/32, B), 256 threads (8 warps). Each warp owns 4 query rows.
// Online softmax; O kept in registers across lanes (lane d holds cols d, d+32).
// Software-pipelined: K/V tile j+1 prefetched into registers during compute of j.
// ---------------------------------------------------------------------------
__global__ void __launch_bounds__(256)
flash_attn_kernel() {
    __shared__ float Qs[32][65];
    __shared__ float Ks[32][65];
    __shared__ float Vs[32][65];

    int b   = blockIdx.y;
    int qt  = blockIdx.x;            // query tile (32 rows)
    int tid = threadIdx.x;
    int warp = tid >> 5, lane = tid & 31;
    const float scale = 0.125f;      // 1/sqrt(64)

    size_t base = (size_t)b * T_ * HS_;

    // Load Q tile: 32x64 = 512 float4
    for (int i = tid; i < 512; i += 256) {
        int r = i >> 4, cg = i & 15;
        float4 v4 = *(const float4*)&g_q[base + (size_t)(qt*32 + r)*HS_ + cg*4];
        Qs[r][cg*4+0] = v4.x; Qs[r][cg*4+1] = v4.y;
        Qs[r][cg*4+2] = v4.z; Qs[r][cg*4+3] = v4.w;
    }

    // Per-thread K/V load coordinates (two float4 per array per tile)
    const int r0 = (tid      ) >> 4, c0 = (tid      ) & 15;
    const int r1 = (tid + 256) >> 4, c1 = (tid + 256) & 15;

    float4 fk0, fk1, fv0, fv1;
    // Prefetch KV tile 0
    {
        size_t off0 = base + (size_t)r0*HS_ + c0*4;
        size_t off1 = base + (size_t)r1*HS_ + c1*4;
        fk0 = *(const float4*)&g_k[off0]; fk1 = *(const float4*)&g_k[off1];
        fv0 = *(const float4*)&g_v[off0]; fv1 = *(const float4*)&g_v[off1];
    }

    float m[4], l[4], o0[4], o1[4];
    #pragma unroll
    for (int rr = 0; rr < 4; ++rr) { m[rr] = -3.0e38f; l[rr] = 0.f; o0[rr] = 0.f; o1[rr] = 0.f; }

    for (int j = 0; j <= qt; ++j) {
        __syncthreads();   // previous tile's compute done (and Q load on j=0)
        // Commit prefetched K/V tile to smem
        Ks[r0][c0*4+0] = fk0.x; Ks[r0][c0*4+1] = fk0.y;
        Ks[r0][c0*4+2] = fk0.z; Ks[r0][c0*4+3] = fk0.w;
        Ks[r1][c1*4+0] = fk1.x; Ks[r1][c1*4+1] = fk1.y;
        Ks[r1][c1*4+2] = fk1.z; Ks[r1][c1*4+3] = fk1.w;
        Vs[r0][c0*4+0] = fv0.x; Vs[r0][c0*4+1] = fv0.y;
        Vs[r0][c0*4+2] = fv0.z; Vs[r0][c0*4+3] = fv0.w;
        Vs[r1][c1*4+0] = fv1.x; Vs[r1][c1*4+1] = fv1.y;
        Vs[r1][c1*4+2] = fv1.z; Vs[r1][c1*4+3] = fv1.w;
        __syncthreads();

        // Prefetch next KV tile (hidden behind compute below)
        if (j < qt) {
            size_t off0 = base + (size_t)((j+1)*32 + r0)*HS_ + c0*4;
            size_t off1 = base + (size_t)((j+1)*32 + r1)*HS_ + c1*4;
            fk0 = *(const float4*)&g_k[off0]; fk1 = *(const float4*)&g_k[off1];
            fv0 = *(const float4*)&g_v[off0]; fv1 = *(const float4*)&g_v[off1];
        }

        #pragma unroll
        for (int rr = 0; rr < 4; ++rr) {
            int row  = warp*4 + rr;
            int grow = qt*32 + row;
            int gcol = j*32 + lane;

            // S[row][lane] = q[row] . k[lane]
            float s = 0.f;
            #pragma unroll
            for (int k = 0; k < HS_; ++k) s += Qs[row][k] * Ks[lane][k];
            s *= scale;
            if (gcol > grow) s = -1.0e30f;

            // warp-wide row max
            float mt = s;
            #pragma unroll
            for (int off = 16; off; off >>= 1)
                mt = fmaxf(mt, __shfl_xor_sync(0xffffffffu, mt, off));
            float mnew  = fmaxf(m[rr], mt);
            float alpha = __expf(m[rr] - mnew);
            float p     = __expf(s - mnew);

            float ps = p;
            #pragma unroll
            for (int off = 16; off; off >>= 1)
                ps += __shfl_xor_sync(0xffffffffu, ps, off);

            l[rr] = l[rr]*alpha + ps;
            m[rr] = mnew;

            float a0 = o0[rr]*alpha, a1 = o1[rr]*alpha;
            #pragma unroll
            for (int c = 0; c < 32; ++c) {
                float pc = __shfl_sync(0xffffffffu, p, c);
                a0 += pc * Vs[c][lane];
                a1 += pc * Vs[c][lane + 32];
            }
            o0[rr] = a0; o1[rr] = a1;
        }
    }

    #pragma unroll
    for (int rr = 0; rr < 4; ++rr) {
        int grow = qt*32 + warp*4 + rr;
        float inv = 1.0f / l[rr];
        g_ho[base + (size_t)grow*HS_ + lane]      = o0[rr] * inv;
        g_ho[base + (size_t)grow*HS_ + lane + 32] = o1[rr] * inv;
    }
}

// ---------------------------------------------------------------------------
// Output projection: out[M,1024] = g_ho[M,64] @ g_wp[64,1024] + bp
// Tile BM=64, BN=64, K=64 fully resident. 256 threads, 4x4 micro-tile,
// packed f32x2 FMA (bit-identical fp32 math, half the fma-pipe issues).
// ---------------------------------------------------------------------------
__global__ void __launch_bounds__(256)
proj_kernel(const float* __restrict__ bp, float* __restrict__ out) {
    __shared__ float Hs[64][65];
    __shared__ float Ws[64][64];

    int tid = threadIdx.x;
    int tx = tid & 15, ty = tid >> 4;
    int row0 = blockIdx.x * 64, col0 = blockIdx.y * 64;

    // Load H tile: 64x64 = 1024 float4
    for (int i = tid; i < 1024; i += 256) {
        int r = i >> 4, cg = i & 15;
        float4 v4 = *(const float4*)&g_ho[(size_t)(row0 + r)*HS_ + cg*4];
        Hs[r][cg*4+0] = v4.x; Hs[r][cg*4+1] = v4.y;
        Hs[r][cg*4+2] = v4.z; Hs[r][cg*4+3] = v4.w;
    }
    // Load W tile
    for (int i = tid; i < 1024; i += 256) {
        int r = i >> 4, cg = i & 15;
        *(float4*)&Ws[r][cg*4] = *(const float4*)&g_wp[(size_t)r*D_ + col0 + cg*4];
    }
    __syncthreads();

    u64_t acc2[4][2] = {};
    #pragma unroll 16
    for (int k = 0; k < 64; ++k) {
        u64_t a2[4], b2[2];
        #pragma unroll
        for (int i = 0; i < 4; ++i) a2[i] = pack_dup(Hs[ty*4+i][k]);
        #pragma unroll
        for (int j2 = 0; j2 < 2; ++j2) b2[j2] = *(const u64_t*)&Ws[k][tx*4 + 2*j2];
        #pragma unroll
        for (int i = 0; i < 4; ++i)
            #pragma unroll
            for (int j2 = 0; j2 < 2; ++j2) fma2(acc2[i][j2], a2[i], b2[j2]);
    }

    float4 bias = *(const float4*)&bp[col0 + tx*4];
    #pragma unroll
    for (int i = 0; i < 4; ++i) {
        size_t r = row0 + ty*4 + i;
        float v0, v1, v2, v3;
        unpack2(acc2[i][0], v0, v1); unpack2(acc2[i][1], v2, v3);
        float4 v4 = make_float4(v0 + bias.x, v1 + bias.y,
                                v2 + bias.z, v3 + bias.w);
        *(float4*)&out[r*D_ + col0 + tx*4] = v4;
    }
}

// ---------------------------------------------------------------------------
extern "C" void kernel_launch(void* const* d_in, const int* in_sizes, int n_in,
                              void* d_out, int out_size) {
    const float* x  = (const float*)d_in[0];
    const float* Wq = (const float*)d_in[1];
    const float* Wk = (const float*)d_in[2];
    const float* Wv = (const float*)d_in[3];
    const float* Wp = (const float*)d_in[4];
    const float* bp = (const float*)d_in[5];
    float* out = (float*)d_out;

    fold_wp_kernel<<<64, 1024>>>(Wp);
    qkv_gemm_kernel<<<M_/64, 256>>>(x, Wq, Wk, Wv);
    flash_attn_kernel<<<dim3(T_/32, B_), 256>>>();
    proj_kernel<<<dim3(M_/64, D_/64), 256>>>(bp, out);

    (void)in_sizes; (void)n_in; (void)out_size;
}